// round 1
// baseline (speedup 1.0000x reference)
#include <cuda_runtime.h>
#include <math_constants.h>

// SoftMinLayer: W = 79998 sliding windows (len 500, step 250) of layer_input,
// each split into 5 segments of 100; banded DTW (|i-j|<=1) over per-cell
// squared L2 distances to segments of S; out = mean(exp(-0.01*sqrt(dtw))).
//
// One warp per window. C[i][j] = sum_e (x[i*100+e] - s[j*100+e])^2 computed
// with packed f32x2 FMA; 13 band cells -> 13 butterfly warp reductions.

#define THREADS 256
#define NWARPS  8          // THREADS/32
#define SEGC    5
#define NF2     50         // float2 elements per segment (100 floats)
#define REM     18         // NF2 - 32 (second k-slice active lanes)

typedef unsigned long long u64;

__device__ __forceinline__ u64 f2_fma(u64 a, u64 b, u64 c) {
    u64 d; asm("fma.rn.f32x2 %0, %1, %2, %3;" : "=l"(d) : "l"(a), "l"(b), "l"(c)); return d;
}
__device__ __forceinline__ u64 f2_add(u64 a, u64 b) {
    u64 d; asm("add.rn.f32x2 %0, %1, %2;" : "=l"(d) : "l"(a), "l"(b)); return d;
}
__device__ __forceinline__ u64 f2_pack(float lo, float hi) {
    u64 d; asm("mov.b64 %0, {%1, %2};" : "=l"(d) : "f"(lo), "f"(hi)); return d;
}
__device__ __forceinline__ float f2_hadd(u64 v) {
    float lo, hi; asm("mov.b64 {%0, %1}, %2;" : "=f"(lo), "=f"(hi) : "l"(v));
    return lo + hi;
}
__device__ __forceinline__ float warp_sum(float v) {
    v += __shfl_xor_sync(0xffffffffu, v, 16);
    v += __shfl_xor_sync(0xffffffffu, v, 8);
    v += __shfl_xor_sync(0xffffffffu, v, 4);
    v += __shfl_xor_sync(0xffffffffu, v, 2);
    v += __shfl_xor_sync(0xffffffffu, v, 1);
    return v;
}

__global__ void zero_kernel(float* out) { out[0] = 0.0f; }

__global__ __launch_bounds__(THREADS)
void softmin_kernel(const float* __restrict__ x, const float* __restrict__ S,
                    float* __restrict__ out, int W, float invW)
{
    const int lane = threadIdx.x & 31;
    const int warp = threadIdx.x >> 5;
    const int w    = blockIdx.x * NWARPS + warp;

    // Preload -S (packed float2) into registers. S is tiny (500 f32, L2-hot).
    const float2* S2 = reinterpret_cast<const float2*>(S);
    u64 ns[SEGC][2];
#pragma unroll
    for (int i = 0; i < SEGC; ++i) {
        float2 a = S2[i * NF2 + lane];
        ns[i][0] = f2_pack(-a.x, -a.y);
        if (lane < REM) {
            float2 b = S2[i * NF2 + 32 + lane];
            ns[i][1] = f2_pack(-b.x, -b.y);
        } else {
            ns[i][1] = 0ull;
        }
    }

    float xi = 0.0f;
    if (w < W) {
        // window start = w*250 floats = w*125 float2 (8B aligned)
        const u64* xw = reinterpret_cast<const u64*>(x) + (size_t)w * 125u;

        u64 acc[SEGC][3];
#pragma unroll
        for (int i = 0; i < SEGC; ++i)
#pragma unroll
            for (int jo = 0; jo < 3; ++jo) acc[i][jo] = 0ull;

#pragma unroll
        for (int i = 0; i < SEGC; ++i) {
            const u64* xs = xw + i * NF2;
            u64 xv = xs[lane];
            if (i > 0)       { u64 d = f2_add(xv, ns[i-1][0]); acc[i][0] = f2_fma(d, d, acc[i][0]); }
                             { u64 d = f2_add(xv, ns[i  ][0]); acc[i][1] = f2_fma(d, d, acc[i][1]); }
            if (i < SEGC-1)  { u64 d = f2_add(xv, ns[i+1][0]); acc[i][2] = f2_fma(d, d, acc[i][2]); }
            if (lane < REM) {
                u64 xv2 = xs[32 + lane];
                if (i > 0)       { u64 d = f2_add(xv2, ns[i-1][1]); acc[i][0] = f2_fma(d, d, acc[i][0]); }
                                 { u64 d = f2_add(xv2, ns[i  ][1]); acc[i][1] = f2_fma(d, d, acc[i][1]); }
                if (i < SEGC-1)  { u64 d = f2_add(xv2, ns[i+1][1]); acc[i][2] = f2_fma(d, d, acc[i][2]); }
            }
        }

        // Reduce the 13 band cells across the warp.
        float C[SEGC][3];
#pragma unroll
        for (int i = 0; i < SEGC; ++i) {
#pragma unroll
            for (int jo = 0; jo < 3; ++jo) {
                const int j = i + jo - 1;
                if (j >= 0 && j < SEGC)
                    C[i][jo] = warp_sum(f2_hadd(acc[i][jo]));
                else
                    C[i][jo] = 0.0f;
            }
        }

        // Banded DTW, fully unrolled, rolling rows in registers.
        const float INF = CUDART_INF_F;
        float row[SEGC + 1];
        row[0] = 0.0f;
#pragma unroll
        for (int r = 1; r <= SEGC; ++r) row[r] = INF;
#pragma unroll
        for (int i = 0; i < SEGC; ++i) {
            float nrow[SEGC + 1];
#pragma unroll
            for (int r = 0; r <= SEGC; ++r) nrow[r] = INF;
            const int lo = (i > 0) ? (i - 1) : 0;
            const int hi = (i + 1 < SEGC) ? (i + 1) : (SEGC - 1);
#pragma unroll
            for (int j = 0; j < SEGC; ++j) {
                if (j >= lo && j <= hi) {
                    float prev = fminf(fminf(row[j + 1], nrow[j]), row[j]);
                    nrow[j + 1] = C[i][j - i + 1] + prev;
                }
            }
#pragma unroll
            for (int r = 0; r <= SEGC; ++r) row[r] = nrow[r];
        }

        xi = __expf(-0.01f * sqrtf(row[SEGC]));
    }

    // Block reduce (xi is warp-uniform) -> one atomicAdd per block.
    __shared__ float sh[NWARPS];
    if (lane == 0) sh[warp] = xi;
    __syncthreads();
    if (threadIdx.x == 0) {
        float s = 0.0f;
#pragma unroll
        for (int i = 0; i < NWARPS; ++i) s += sh[i];
        atomicAdd(out, s * invW);
    }
}

extern "C" void kernel_launch(void* const* d_in, const int* in_sizes, int n_in,
                              void* d_out, int out_size)
{
    const float* x = (const float*)d_in[0];
    const float* S = (const float*)d_in[1];
    float* out = (float*)d_out;

    const int Q    = in_sizes[0];
    const int L    = in_sizes[1];     // 500
    const int step = L / 2;           // 250
    const int W    = (Q - L + step - 1) / step;   // arange(0, Q-L, step) count
    const float invW = 1.0f / (float)W;

    zero_kernel<<<1, 1>>>(out);
    const int blocks = (W + NWARPS - 1) / NWARPS;
    softmin_kernel<<<blocks, THREADS>>>(x, S, out, W, invW);
}

// round 2
// speedup vs baseline: 1.2805x; 1.2805x over previous
#include <cuda_runtime.h>
#include <math_constants.h>

// SoftMinLayer: W = 79998 sliding windows (len 500, step 250) of layer_input,
// 5 segments of 100; banded DTW (|i-j|<=1) over per-cell squared L2 distances
// to segments of S; out = mean(exp(-0.01*sqrt(dtw))).
//
// One warp per window, PERSISTENT (grid-stride over windows).
// 13 band-cell dots accumulated with packed f32x2 FMA, then ALL 13 reduced
// together with a fold-tree (15 shfl total instead of 65).

#define THREADS 256
#define NWARPS  8
#define SEGC    5
#define NF2     50         // float2 per segment
#define REM     18         // NF2 - 32
#define BLOCKS  1184       // 8 * 148

typedef unsigned long long u64;

__device__ __forceinline__ u64 f2_fma(u64 a, u64 b, u64 c) {
    u64 d; asm("fma.rn.f32x2 %0, %1, %2, %3;" : "=l"(d) : "l"(a), "l"(b), "l"(c)); return d;
}
__device__ __forceinline__ u64 f2_add(u64 a, u64 b) {
    u64 d; asm("add.rn.f32x2 %0, %1, %2;" : "=l"(d) : "l"(a), "l"(b)); return d;
}
__device__ __forceinline__ u64 f2_pack(float lo, float hi) {
    u64 d; asm("mov.b64 %0, {%1, %2};" : "=l"(d) : "f"(lo), "f"(hi)); return d;
}
__device__ __forceinline__ float f2_hadd(u64 v) {
    float lo, hi; asm("mov.b64 {%0, %1}, %2;" : "=f"(lo), "=f"(hi) : "l"(v));
    return lo + hi;
}

// Fold step: pair two reduction streams A,B at butterfly offset o.
__device__ __forceinline__ float foldstep(float A, float B, bool p, int o) {
    float v = p ? B : A;
    float u = p ? A : B;
    return v + __shfl_xor_sync(0xffffffffu, u, o);
}

// After full fold, value n (n = 8*b1 + 4*b2 + 2*b3 + b4) lives at lane
// 2*b1 + 4*b2 + 8*b3 + 16*b4.
#define SRCLANE(n) ((((n) >> 3) & 1) * 2 + (((n) >> 2) & 1) * 4 + \
                    (((n) >> 1) & 1) * 8 + ((n) & 1) * 16)

__global__ void zero_kernel(float* out) { out[0] = 0.0f; }

__global__ __launch_bounds__(THREADS, 3)
void softmin_kernel(const float* __restrict__ x, const float* __restrict__ S,
                    float* __restrict__ out, int W, float invW)
{
    const int lane = threadIdx.x & 31;
    const int warp = threadIdx.x >> 5;
    const int gw   = blockIdx.x * NWARPS + warp;
    const int TW   = gridDim.x * NWARPS;

    const float2* S2 = reinterpret_cast<const float2*>(S);
    u64 ns[SEGC][2];
#pragma unroll
    for (int i = 0; i < SEGC; ++i) {
        float2 a = S2[i * NF2 + lane];
        ns[i][0] = f2_pack(-a.x, -a.y);
        if (lane < REM) {
            float2 b = S2[i * NF2 + 32 + lane];
            ns[i][1] = f2_pack(-b.x, -b.y);
        } else {
            ns[i][1] = 0ull;
        }
    }

    const bool p16 = (lane & 16) != 0;
    const bool p8  = (lane & 8)  != 0;
    const bool p4  = (lane & 4)  != 0;
    const bool p2  = (lane & 2)  != 0;

    float xsum = 0.0f;

    for (int w = gw; w < W; w += TW) {
        const u64* xw = reinterpret_cast<const u64*>(x) + (size_t)w * 125u;

        u64 acc[13];
#pragma unroll
        for (int c = 0; c < 13; ++c) acc[c] = 0ull;

        // cell index: i=0 -> {1:0, 2:1}; i>=1 -> jo -> i*3-1+jo  (13 cells)
#pragma unroll
        for (int i = 0; i < SEGC; ++i) {
            const int c0 = (i == 0) ? -1 : (i * 3 - 1);
            const int c1 = (i == 0) ? 0  : (i * 3);
            const int c2 = (i == SEGC - 1) ? -1 : ((i == 0) ? 1 : (i * 3 + 1));
            const u64* xs = xw + i * NF2;
            u64 xv = xs[lane];
            if (c0 >= 0) { u64 d = f2_add(xv, ns[i-1][0]); acc[c0] = f2_fma(d, d, acc[c0]); }
                         { u64 d = f2_add(xv, ns[i  ][0]); acc[c1] = f2_fma(d, d, acc[c1]); }
            if (c2 >= 0) { u64 d = f2_add(xv, ns[i+1][0]); acc[c2] = f2_fma(d, d, acc[c2]); }
            if (lane < REM) {
                u64 xv2 = xs[32 + lane];
                if (c0 >= 0) { u64 d = f2_add(xv2, ns[i-1][1]); acc[c0] = f2_fma(d, d, acc[c0]); }
                             { u64 d = f2_add(xv2, ns[i  ][1]); acc[c1] = f2_fma(d, d, acc[c1]); }
                if (c2 >= 0) { u64 d = f2_add(xv2, ns[i+1][1]); acc[c2] = f2_fma(d, d, acc[c2]); }
            }
        }

        float a0  = f2_hadd(acc[0]),  a1  = f2_hadd(acc[1]),  a2  = f2_hadd(acc[2]);
        float a3  = f2_hadd(acc[3]),  a4  = f2_hadd(acc[4]),  a5  = f2_hadd(acc[5]);
        float a6  = f2_hadd(acc[6]),  a7  = f2_hadd(acc[7]),  a8  = f2_hadd(acc[8]);
        float a9  = f2_hadd(acc[9]),  a10 = f2_hadd(acc[10]), a11 = f2_hadd(acc[11]);
        float a12 = f2_hadd(acc[12]);

        float q0 = foldstep(a0,  a1,  p16, 16);
        float q1 = foldstep(a2,  a3,  p16, 16);
        float q2 = foldstep(a4,  a5,  p16, 16);
        float q3 = foldstep(a6,  a7,  p16, 16);
        float q4 = foldstep(a8,  a9,  p16, 16);
        float q5 = foldstep(a10, a11, p16, 16);
        float q6 = foldstep(a12, 0.0f, p16, 16);

        float r0 = foldstep(q0, q1, p8, 8);
        float r1 = foldstep(q2, q3, p8, 8);
        float r2 = foldstep(q4, q5, p8, 8);
        float r3 = foldstep(q6, 0.0f, p8, 8);

        float t0 = foldstep(r0, r1, p4, 4);
        float t1 = foldstep(r2, r3, p4, 4);

        float u0 = foldstep(t0, t1, p2, 2);
        float fin = u0 + __shfl_xor_sync(0xffffffffu, u0, 1);

        float C13[13];
#pragma unroll
        for (int n = 0; n < 13; ++n)
            C13[n] = __shfl_sync(0xffffffffu, fin, SRCLANE(n));

        float C[SEGC][3];
#pragma unroll
        for (int i = 0; i < SEGC; ++i) {
#pragma unroll
            for (int jo = 0; jo < 3; ++jo) {
                const int j = i + jo - 1;
                if (j >= 0 && j < SEGC) {
                    const int c = (i == 0) ? (jo - 1) : (i * 3 - 1 + jo);
                    C[i][jo] = C13[c];
                } else {
                    C[i][jo] = 0.0f;
                }
            }
        }

        const float INF = CUDART_INF_F;
        float row[SEGC + 1];
        row[0] = 0.0f;
#pragma unroll
        for (int r = 1; r <= SEGC; ++r) row[r] = INF;
#pragma unroll
        for (int i = 0; i < SEGC; ++i) {
            float nrow[SEGC + 1];
#pragma unroll
            for (int r = 0; r <= SEGC; ++r) nrow[r] = INF;
            const int lo = (i > 0) ? (i - 1) : 0;
            const int hi = (i + 1 < SEGC) ? (i + 1) : (SEGC - 1);
#pragma unroll
            for (int j = 0; j < SEGC; ++j) {
                if (j >= lo && j <= hi) {
                    float prev = fminf(fminf(row[j + 1], nrow[j]), row[j]);
                    nrow[j + 1] = C[i][j - i + 1] + prev;
                }
            }
#pragma unroll
            for (int r = 0; r <= SEGC; ++r) row[r] = nrow[r];
        }

        xsum += __expf(-0.01f * sqrtf(row[SEGC]));
    }

    __shared__ float sh[NWARPS];
    if (lane == 0) sh[warp] = xsum;
    __syncthreads();
    if (threadIdx.x == 0) {
        float s = 0.0f;
#pragma unroll
        for (int i = 0; i < NWARPS; ++i) s += sh[i];
        atomicAdd(out, s * invW);
    }
}

extern "C" void kernel_launch(void* const* d_in, const int* in_sizes, int n_in,
                              void* d_out, int out_size)
{
    const float* x = (const float*)d_in[0];
    const float* S = (const float*)d_in[1];
    float* out = (float*)d_out;

    const int Q    = in_sizes[0];
    const int L    = in_sizes[1];     // 500
    const int step = L / 2;           // 250
    const int W    = (Q - L + step - 1) / step;
    const float invW = 1.0f / (float)W;

    zero_kernel<<<1, 1>>>(out);
    softmin_kernel<<<BLOCKS, THREADS>>>(x, S, out, W, invW);
}